// round 13
// baseline (speedup 1.0000x reference)
#include <cuda_runtime.h>
#include <cuda_bf16.h>
#include <cstdint>

// Problem constants
#define SN 96
#define NB 32
#define MM 3072
#define OLEN 48
#define SLT 143
#define HH 128
#define DD 32
#define KK 288       // fused K = 2H + D
#define NG 768       // 6H gate cols
#define NX (NB * SN * OLEN * DD)

#define MT 64        // block M tile
#define NT 96        // block N tile
#define ARS 80       // smem row stride bytes (32 bf16 + 16B pad)
#define STG_A (MT * ARS)            // 5120
#define STG_B (NT * ARS)            // 7680
#define STG_BYTES (STG_A + STG_B)   // 12800
#define NSTG 3
#define SMEM_BYTES (NSTG * STG_BYTES)   // 38400

// ---------------- device scratch ----------------
__device__ __nv_bfloat16 g_Wh[NG * KK];
__device__ __nv_bfloat16 g_Wl[NG * KK];
__device__ float g_bias[NG];
__device__ float g_hrow[2][MM * HH];
__device__ float g_hcol[2][MM * HH];
__device__ __nv_bfloat16 g_hr_h[2][MM * HH], g_hr_l[2][MM * HH];
__device__ __nv_bfloat16 g_hc_h[2][MM * HH], g_hc_l[2][MM * HH];
__device__ __nv_bfloat16 g_x_h[NX], g_x_l[NX];

// ---------------- helpers ----------------
__device__ __forceinline__ uint32_t smem_u32(const void* p) {
    uint32_t a;
    asm("{ .reg .u64 t; cvta.to.shared.u64 t, %1; cvt.u32.u64 %0, t; }" : "=r"(a) : "l"(p));
    return a;
}
__device__ __forceinline__ void cp_async16(uint32_t dst, const void* src, bool valid) {
    int sz = valid ? 16 : 0;
    asm volatile("cp.async.cg.shared.global [%0], [%1], 16, %2;"
                 :: "r"(dst), "l"(src), "r"(sz) : "memory");
}
#define CP_COMMIT()  asm volatile("cp.async.commit_group;" ::: "memory")
#define CP_WAIT1()   asm volatile("cp.async.wait_group 1;" ::: "memory")
__device__ __forceinline__ void ldsm_x4(uint32_t& r0, uint32_t& r1, uint32_t& r2, uint32_t& r3,
                                        uint32_t addr) {
    asm volatile("ldmatrix.sync.aligned.m8n8.x4.shared.b16 {%0,%1,%2,%3}, [%4];"
                 : "=r"(r0), "=r"(r1), "=r"(r2), "=r"(r3) : "r"(addr));
}
__device__ __forceinline__ void ldsm_x2(uint32_t& r0, uint32_t& r1, uint32_t addr) {
    asm volatile("ldmatrix.sync.aligned.m8n8.x2.shared.b16 {%0,%1}, [%2];"
                 : "=r"(r0), "=r"(r1) : "r"(addr));
}
__device__ __forceinline__ void mma16816(float* c, uint32_t a0, uint32_t a1, uint32_t a2,
                                         uint32_t a3, uint32_t b0, uint32_t b1) {
    asm volatile(
        "mma.sync.aligned.m16n8k16.row.col.f32.bf16.bf16.f32 "
        "{%0,%1,%2,%3}, {%4,%5,%6,%7}, {%8,%9}, {%0,%1,%2,%3};"
        : "+f"(c[0]), "+f"(c[1]), "+f"(c[2]), "+f"(c[3])
        : "r"(a0), "r"(a1), "r"(a2), "r"(a3), "r"(b0), "r"(b1));
}
__device__ __forceinline__ float tanh_ap(float x) {
    float y;
    asm("tanh.approx.f32 %0, %1;" : "=f"(y) : "f"(x));
    return y;
}
__device__ __forceinline__ float sigmoid_f(float x) {
    return fmaf(0.5f, tanh_ap(0.5f * x), 0.5f);
}

// ---------------- init ----------------
__global__ void zero_all_kernel() {
    const __nv_bfloat16 bz = __float2bfloat16(0.f);
    int n = MM * HH;
    for (int i = blockIdx.x * blockDim.x + threadIdx.x; i < n; i += gridDim.x * blockDim.x) {
        g_hrow[0][i] = 0.f; g_hrow[1][i] = 0.f;
        g_hcol[0][i] = 0.f; g_hcol[1][i] = 0.f;
        g_hr_h[0][i] = bz; g_hr_h[1][i] = bz;
        g_hr_l[0][i] = bz; g_hr_l[1][i] = bz;
        g_hc_h[0][i] = bz; g_hc_h[1][i] = bz;
        g_hc_l[0][i] = bz; g_hc_l[1][i] = bz;
    }
}

__global__ void prep_x_kernel(const float* __restrict__ input) {
    for (int i = blockIdx.x * blockDim.x + threadIdx.x; i < NX; i += gridDim.x * blockDim.x) {
        float v = input[i];
        __nv_bfloat16 hi = __float2bfloat16(v);
        g_x_h[i] = hi;
        g_x_l[i] = __float2bfloat16(v - __bfloat162float(hi));
    }
}

// ---------------- prep: fused weights, mma-epilogue column permutation ----------------
// Warp tile 32x24 (3 n8 tiles): cp -> nb=cp/96, local=cp%96, wN=local/24, r2=local%24,
//   p=r2/8 (pair type), c=(r2%8)/2, e=r2&1
//   u = nb*16 + wN*4 + c,  original gate g=p*2+e, oc = g*128 + u
// K layout: [0:128)=h_row, [128:256)=h_col, [256:288)=x
__global__ void prep_weights_kernel(
    const float* __restrict__ Wf,  const float* __restrict__ bf,
    const float* __restrict__ Wrm, const float* __restrict__ brm,
    const float* __restrict__ Wcm, const float* __restrict__ bcm,
    const float* __restrict__ Wrxm, const float* __restrict__ brxm,
    const float* __restrict__ Wcxm, const float* __restrict__ bcxm)
{
    int cp = blockIdx.x;              // 0..767
    int nb = cp / 96, local = cp % 96;
    int wN = local / 24, r2 = local % 24;
    int p = r2 >> 3, ce = r2 & 7;
    int c = ce >> 1, e = ce & 1;
    int u = nb * 16 + wN * 4 + c;
    int oc = (p * 2 + e) * 128 + u;

    __shared__ float sWf[KK];
    for (int i = threadIdx.x; i < KK; i += blockDim.x) sWf[i] = Wf[oc * KK + i];
    __syncthreads();

    int k = threadIdx.x;             // 288 threads
    float acc = 0.f;
    if (k < HH) {
        #pragma unroll 4
        for (int h = 0; h < HH; h++) acc += Wrm[h * HH + k] * sWf[h];
    } else if (k < 2 * HH) {
        int kk = k - HH;
        #pragma unroll 4
        for (int h = 0; h < HH; h++) acc += Wcm[h * HH + kk] * sWf[HH + h];
    } else {
        int d = k - 2 * HH;
        #pragma unroll 4
        for (int h = 0; h < HH; h++)
            acc += Wrxm[h * DD + d] * sWf[h] + Wcxm[h * DD + d] * sWf[HH + h];
        acc += sWf[2 * HH + d];
    }
    __nv_bfloat16 hi = __float2bfloat16(acc);
    g_Wh[cp * KK + k] = hi;
    g_Wl[cp * KK + k] = __float2bfloat16(acc - __bfloat162float(hi));

    if (threadIdx.x == 0) {
        float bacc = bf[oc];
        for (int h = 0; h < HH; h++)
            bacc += (brxm[h] + brm[h]) * sWf[h] + (bcxm[h] + bcm[h]) * sWf[HH + h];
        g_bias[cp] = bacc;
    }
}

// ---------------- per-step: HMMA GEMM + gating, cp.async 3-stage pipeline ----------------
// grid (8 n-tiles of 96, 48 m-tiles of 64) = 384 blocks, 256 threads = 8 warps (2M x 4N),
// warp tile 32x24 (2 m16 x 3 n8). K' = 864 (3 passes x 288), 27 chunks of k32.
__global__ __launch_bounds__(256, 3) void step_kernel(
    float* __restrict__ out, int t, int pin, int write_hidden)
{
    extern __shared__ __align__(16) char sm[];
    const uint32_t sb = smem_u32(sm);

    const int tid   = threadIdx.x;
    const int lane  = tid & 31;
    const int wid   = tid >> 5;
    const int warpM = wid & 1;         // 0..1
    const int warpN = wid >> 1;        // 0..3
    const int mBase = blockIdx.y * MT;
    const int nBase = blockIdx.x * NT;

    const int g4 = lane >> 2, c4 = lane & 3;
    const int grp = lane >> 3, lr = lane & 7;

    // ldmatrix lane base addresses (stage 0; add stage offset per chunk)
    const uint32_t aBase = sb + (warpM * 32 + ((grp & 1) << 3) + lr) * ARS + ((grp >> 1) << 4);
    const uint32_t bBase = sb + STG_A + (warpN * 24 + ((grp >> 1) << 3) + lr) * ARS + ((grp & 1) << 4);

    float acc[2][3][4];
    #pragma unroll
    for (int i = 0; i < 2; i++)
        #pragma unroll
        for (int j = 0; j < 3; j++)
            #pragma unroll
            for (int e = 0; e < 4; e++) acc[i][j][e] = 0.f;

    // ---- cp.async staging of one chunk (extended-K cc) into stage s ----
    auto stage_chunk = [&](int cc, int s) {
        int p = cc / 9, kc = cc - p * 9;
        uint32_t base = sb + s * STG_BYTES;
        // A: 64 rows x 32 bf16 = 256 16B-slots, 1 per thread
        {
            int row = tid >> 2, slot = tid & 3;
            int m = mBase + row;
            uint32_t dst = base + row * ARS + slot * 16;
            if (kc < 8) {
                bool isRow = kc < 4;
                int kk = (isRow ? kc : kc - 4) * 32 + slot * 8;
                const __nv_bfloat16* src = isRow ? ((p == 1) ? g_hr_l[pin] : g_hr_h[pin])
                                                 : ((p == 1) ? g_hc_l[pin] : g_hc_h[pin]);
                cp_async16(dst, src + m * HH + kk, true);
            } else {
                int r = m >> 5, b = m & 31;
                int c = t - r;
                bool valid = (c >= 0 && c < OLEN);
                const __nv_bfloat16* src = (p == 1) ? g_x_l : g_x_h;
                const __nv_bfloat16* sp = src + ((b * SN + r) * OLEN + (valid ? c : 0)) * DD + slot * 8;
                cp_async16(dst, sp, valid);
            }
        }
        // B: 96 rows x 32 bf16 = 384 16B-slots, 1.5 per thread
        const __nv_bfloat16* w = (p == 2) ? g_Wl : g_Wh;
        {
            int row = tid >> 2, slot = tid & 3;
            uint32_t dst = base + STG_A + row * ARS + slot * 16;
            cp_async16(dst, w + (nBase + row) * KK + kc * 32 + slot * 8, true);
        }
        if (tid < 128) {
            int lin = 256 + tid;
            int row = lin >> 2, slot = lin & 3;
            uint32_t dst = base + STG_A + row * ARS + slot * 16;
            cp_async16(dst, w + (nBase + row) * KK + kc * 32 + slot * 8, true);
        }
        CP_COMMIT();
    };

    // ---- prologue: stage chunks 0 and 1 ----
    stage_chunk(0, 0);
    stage_chunk(1, 1);

    for (int cc = 0; cc < 27; ++cc) {
        CP_WAIT1();            // chunk cc landed (cc+1 may be in flight)
        __syncthreads();       // all warps see it; stage (cc+2)%3 fully consumed

        if (cc + 2 < 27) stage_chunk(cc + 2, (cc + 2) % NSTG);

        // compute chunk cc from stage cc%3
        const uint32_t soff = (uint32_t)(cc % NSTG) * STG_BYTES;
        const uint32_t aB = aBase + soff;
        const uint32_t bB = bBase + soff;
        #pragma unroll
        for (int ks = 0; ks < 2; ++ks) {
            uint32_t a[2][4];
            #pragma unroll
            for (int mt = 0; mt < 2; ++mt)
                ldsm_x4(a[mt][0], a[mt][1], a[mt][2], a[mt][3],
                        aB + mt * (16 * ARS) + ks * 32);
            uint32_t bt[3][2];
            {
                uint32_t r0, r1, r2, r3;
                ldsm_x4(r0, r1, r2, r3, bB + ks * 32);          // rows 0-15 of slab
                bt[0][0] = r0; bt[0][1] = r1;
                bt[1][0] = r2; bt[1][1] = r3;
                uint32_t s0, s1;
                ldsm_x2(s0, s1, bB + 16 * ARS + ks * 32);       // rows 16-23 of slab
                bt[2][0] = s0; bt[2][1] = s1;
            }
            #pragma unroll
            for (int mt = 0; mt < 2; ++mt)
                #pragma unroll
                for (int nt = 0; nt < 3; ++nt)
                    mma16816(acc[mt][nt], a[mt][0], a[mt][1], a[mt][2], a[mt][3],
                             bt[nt][0], bt[nt][1]);
        }
    }

    // ---- epilogue: bias + gating + state update + outputs ----
    const float* __restrict__ hrow_in = g_hrow[pin];
    const float* __restrict__ hcol_in = g_hcol[pin];
    float* __restrict__ hrow_out = g_hrow[pin ^ 1];
    float* __restrict__ hcol_out = g_hcol[pin ^ 1];
    __nv_bfloat16* __restrict__ hr_h_out = g_hr_h[pin ^ 1];
    __nv_bfloat16* __restrict__ hr_l_out = g_hr_l[pin ^ 1];
    __nv_bfloat16* __restrict__ hc_h_out = g_hc_h[pin ^ 1];
    __nv_bfloat16* __restrict__ hc_l_out = g_hc_l[pin ^ 1];

    float bl[3][2];
    #pragma unroll
    for (int p = 0; p < 3; ++p)
        #pragma unroll
        for (int e = 0; e < 2; ++e)
            bl[p][e] = g_bias[nBase + warpN * 24 + p * 8 + c4 * 2 + e];

    const long long HR_BASE = (long long)MM * SLT * 256;
    const long long HC_BASE = HR_BASE + (long long)NB * SN * HH;

    const int U = blockIdx.x * 16 + warpN * 4 + c4;   // global hidden unit

    #pragma unroll
    for (int mt = 0; mt < 2; ++mt) {
        #pragma unroll
        for (int h = 0; h < 2; ++h) {
            const int m = mBase + warpM * 32 + mt * 16 + h * 8 + g4;
            const int r = m >> 5, b = m & 31;
            int ms = m + NB; if (ms >= MM) ms -= MM;
            const long long ob = ((long long)m * SLT + t) * 256;

            float a_ur = acc[mt][0][h * 2 + 0] + bl[0][0];
            float a_or = acc[mt][0][h * 2 + 1] + bl[0][1];
            float a_uc = acc[mt][1][h * 2 + 0] + bl[1][0];
            float a_oc = acc[mt][1][h * 2 + 1] + bl[1][1];
            float a_ir = acc[mt][2][h * 2 + 0] + bl[2][0];
            float a_ic = acc[mt][2][h * 2 + 1] + bl[2][1];

            float hr = hrow_in[m * HH + U];
            float hc = hcol_in[m * HH + U];

            float ur = sigmoid_f(a_ur);
            float og = sigmoid_f(a_or);
            float uc = sigmoid_f(a_uc);
            float oc = sigmoid_f(a_oc);
            float ir = tanh_ap(a_ir);
            float ic = tanh_ap(a_ic);

            float hrn = tanh_ap((1.f - ur) * hr + ur * ir) * og;
            float hcn = tanh_ap((1.f - uc) * hc + uc * ic) * oc;

            out[ob + U]       = hrn;
            out[ob + 128 + U] = hcn;

            hrow_out[m * HH + U] = hrn;
            hcol_out[ms * HH + U] = hcn;

            __nv_bfloat16 rh = __float2bfloat16(hrn);
            hr_h_out[m * HH + U] = rh;
            hr_l_out[m * HH + U] = __float2bfloat16(hrn - __bfloat162float(rh));
            __nv_bfloat16 ch = __float2bfloat16(hcn);
            hc_h_out[ms * HH + U] = ch;
            hc_l_out[ms * HH + U] = __float2bfloat16(hcn - __bfloat162float(ch));

            if (write_hidden) {
                if (t - r == OLEN - 1)
                    out[HR_BASE + ((long long)b * SN + r) * HH + U] = hrn;
                if (r == SN - 1 && t >= SN - 1)
                    out[HC_BASE + ((long long)b * OLEN + (t - (SN - 1))) * HH + U] = hcn;
            }
        }
    }
}

// ---------------- launch ----------------
extern "C" void kernel_launch(void* const* d_in, const int* in_sizes, int n_in,
                              void* d_out, int out_size) {
    const float* input = (const float*)d_in[0];
    const float* Wf    = (const float*)d_in[1];
    const float* bf    = (const float*)d_in[2];
    const float* Wrm   = (const float*)d_in[3];
    const float* brm   = (const float*)d_in[4];
    const float* Wcm   = (const float*)d_in[5];
    const float* bcm   = (const float*)d_in[6];
    const float* Wrxm  = (const float*)d_in[7];
    const float* brxm  = (const float*)d_in[8];
    const float* Wcxm  = (const float*)d_in[9];
    const float* bcxm  = (const float*)d_in[10];
    float* out = (float*)d_out;

    long long need = (long long)MM * SLT * 256 + (long long)NB * SN * HH + (long long)NB * OLEN * HH;
    int write_hidden = ((long long)out_size >= need) ? 1 : 0;

    static int attr_set = 0;
    if (!attr_set) {
        cudaFuncSetAttribute(step_kernel, cudaFuncAttributeMaxDynamicSharedMemorySize,
                             SMEM_BYTES);
        attr_set = 1;
    }

    zero_all_kernel<<<256, 256>>>();
    prep_x_kernel<<<256, 256>>>(input);
    prep_weights_kernel<<<NG, KK>>>(Wf, bf, Wrm, brm, Wcm, bcm, Wrxm, brxm, Wcxm, bcxm);

    dim3 grid(8, 48);
    for (int t = 0; t < SLT; ++t) {
        step_kernel<<<grid, 256, SMEM_BYTES>>>(out, t, t & 1, write_hidden);
    }
}

// round 15
// speedup vs baseline: 1.1003x; 1.1003x over previous
#include <cuda_runtime.h>
#include <cuda_bf16.h>
#include <cstdint>

// Problem constants
#define SN 96
#define NB 32
#define MM 3072
#define OLEN 48
#define SLT 143
#define HH 128
#define DD 32
#define KK 288       // fused K = 2H + D
#define NG 768       // 6H gate cols
#define NX (NB * SN * OLEN * DD)

#define MT 64        // block M tile
#define NT 96        // block N tile
#define ARS 80       // smem row stride bytes (32 bf16 + 16B pad)
#define STG_A (MT * ARS)            // 5120
#define STG_B (NT * ARS)            // 7680
#define STG_BYTES (STG_A + STG_B)   // 12800
#define NSTG 4
#define SMEM_BYTES (NSTG * STG_BYTES)   // 51200

// ---------------- device scratch ----------------
__device__ __nv_bfloat16 g_Wh[NG * KK];
__device__ __nv_bfloat16 g_Wl[NG * KK];
__device__ float g_bias[NG];
__device__ float g_hrow[2][MM * HH];
__device__ float g_hcol[2][MM * HH];
__device__ __nv_bfloat16 g_hr_h[2][MM * HH], g_hr_l[2][MM * HH];
__device__ __nv_bfloat16 g_hc_h[2][MM * HH], g_hc_l[2][MM * HH];
__device__ __nv_bfloat16 g_x_h[NX], g_x_l[NX];

// ---------------- helpers ----------------
__device__ __forceinline__ uint32_t smem_u32(const void* p) {
    uint32_t a;
    asm("{ .reg .u64 t; cvta.to.shared.u64 t, %1; cvt.u32.u64 %0, t; }" : "=r"(a) : "l"(p));
    return a;
}
__device__ __forceinline__ void cp_async16(uint32_t dst, const void* src, bool valid) {
    int sz = valid ? 16 : 0;
    asm volatile("cp.async.cg.shared.global [%0], [%1], 16, %2;"
                 :: "r"(dst), "l"(src), "r"(sz) : "memory");
}
#define CP_COMMIT()  asm volatile("cp.async.commit_group;" ::: "memory")
#define CP_WAIT2()   asm volatile("cp.async.wait_group 2;" ::: "memory")
__device__ __forceinline__ void ldsm_x4(uint32_t& r0, uint32_t& r1, uint32_t& r2, uint32_t& r3,
                                        uint32_t addr) {
    asm volatile("ldmatrix.sync.aligned.m8n8.x4.shared.b16 {%0,%1,%2,%3}, [%4];"
                 : "=r"(r0), "=r"(r1), "=r"(r2), "=r"(r3) : "r"(addr));
}
__device__ __forceinline__ void mma16816(float* c, uint32_t a0, uint32_t a1, uint32_t a2,
                                         uint32_t a3, uint32_t b0, uint32_t b1) {
    asm volatile(
        "mma.sync.aligned.m16n8k16.row.col.f32.bf16.bf16.f32 "
        "{%0,%1,%2,%3}, {%4,%5,%6,%7}, {%8,%9}, {%0,%1,%2,%3};"
        : "+f"(c[0]), "+f"(c[1]), "+f"(c[2]), "+f"(c[3])
        : "r"(a0), "r"(a1), "r"(a2), "r"(a3), "r"(b0), "r"(b1));
}
__device__ __forceinline__ float tanh_ap(float x) {
    float y;
    asm("tanh.approx.f32 %0, %1;" : "=f"(y) : "f"(x));
    return y;
}
__device__ __forceinline__ float sigmoid_f(float x) {
    return fmaf(0.5f, tanh_ap(0.5f * x), 0.5f);
}

// ---------------- init ----------------
__global__ void zero_all_kernel() {
    const __nv_bfloat16 bz = __float2bfloat16(0.f);
    int n = MM * HH;
    for (int i = blockIdx.x * blockDim.x + threadIdx.x; i < n; i += gridDim.x * blockDim.x) {
        g_hrow[0][i] = 0.f; g_hrow[1][i] = 0.f;
        g_hcol[0][i] = 0.f; g_hcol[1][i] = 0.f;
        g_hr_h[0][i] = bz; g_hr_h[1][i] = bz;
        g_hr_l[0][i] = bz; g_hr_l[1][i] = bz;
        g_hc_h[0][i] = bz; g_hc_h[1][i] = bz;
        g_hc_l[0][i] = bz; g_hc_l[1][i] = bz;
    }
}

__global__ void prep_x_kernel(const float* __restrict__ input) {
    for (int i = blockIdx.x * blockDim.x + threadIdx.x; i < NX; i += gridDim.x * blockDim.x) {
        float v = input[i];
        __nv_bfloat16 hi = __float2bfloat16(v);
        g_x_h[i] = hi;
        g_x_l[i] = __float2bfloat16(v - __bfloat162float(hi));
    }
}

// ---------------- prep: fused weights, mma-epilogue column permutation ----------------
// NT=96: cp -> nb=cp/96, local=cp%96, wN=local/48, r2=local%48,
//        tile=r2/8 (p=tile%3, q=tile/3), c=(r2%8)/2, e=r2&1
//        u = nb*16 + wN*8 + q*4 + c,  original gate g=p*2+e, oc = g*128 + u
// K layout: [0:128)=h_row, [128:256)=h_col, [256:288)=x
__global__ void prep_weights_kernel(
    const float* __restrict__ Wf,  const float* __restrict__ bf,
    const float* __restrict__ Wrm, const float* __restrict__ brm,
    const float* __restrict__ Wcm, const float* __restrict__ bcm,
    const float* __restrict__ Wrxm, const float* __restrict__ brxm,
    const float* __restrict__ Wcxm, const float* __restrict__ bcxm)
{
    int cp = blockIdx.x;              // 0..767
    int nb = cp / 96, local = cp % 96;
    int wN = local / 48, r2 = local % 48;
    int tile = r2 >> 3, ce = r2 & 7;
    int c = ce >> 1, e = ce & 1;
    int p = tile % 3, q = tile / 3;
    int u = nb * 16 + wN * 8 + q * 4 + c;
    int oc = (p * 2 + e) * 128 + u;

    __shared__ float sWf[KK];
    for (int i = threadIdx.x; i < KK; i += blockDim.x) sWf[i] = Wf[oc * KK + i];
    __syncthreads();

    int k = threadIdx.x;             // 288 threads
    float acc = 0.f;
    if (k < HH) {
        #pragma unroll 4
        for (int h = 0; h < HH; h++) acc += Wrm[h * HH + k] * sWf[h];
    } else if (k < 2 * HH) {
        int kk = k - HH;
        #pragma unroll 4
        for (int h = 0; h < HH; h++) acc += Wcm[h * HH + kk] * sWf[HH + h];
    } else {
        int d = k - 2 * HH;
        #pragma unroll 4
        for (int h = 0; h < HH; h++)
            acc += Wrxm[h * DD + d] * sWf[h] + Wcxm[h * DD + d] * sWf[HH + h];
        acc += sWf[2 * HH + d];
    }
    __nv_bfloat16 hi = __float2bfloat16(acc);
    g_Wh[cp * KK + k] = hi;
    g_Wl[cp * KK + k] = __float2bfloat16(acc - __bfloat162float(hi));

    if (threadIdx.x == 0) {
        float bacc = bf[oc];
        for (int h = 0; h < HH; h++)
            bacc += (brxm[h] + brm[h]) * sWf[h] + (bcxm[h] + bcm[h]) * sWf[HH + h];
        g_bias[cp] = bacc;
    }
}

// ---------------- per-step: HMMA GEMM + gating, cp.async 4-stage pipeline ----------------
// grid (8 n-tiles of 96, 48 m-tiles of 64) = 384 blocks, 128 threads = 4 warps (2M x 2N),
// warp tile 32x48 (2 m16 x 6 n8). K' = 864 (3 passes x 288), 27 chunks of k32.
__global__ __launch_bounds__(128, 4) void step_kernel(
    float* __restrict__ out, int t, int pin, int write_hidden)
{
    extern __shared__ __align__(16) char sm[];
    const uint32_t sb = smem_u32(sm);

    const int tid   = threadIdx.x;
    const int lane  = tid & 31;
    const int wid   = tid >> 5;
    const int warpM = wid & 1;         // 0..1
    const int warpN = wid >> 1;        // 0..1
    const int mBase = blockIdx.y * MT;
    const int nBase = blockIdx.x * NT;

    const int g4 = lane >> 2, c4 = lane & 3;
    const int grp = lane >> 3, lr = lane & 7;

    // ldmatrix lane base addresses (stage 0; add stage offset per chunk)
    const uint32_t aBase = sb + (warpM * 32 + ((grp & 1) << 3) + lr) * ARS + ((grp >> 1) << 4);
    const uint32_t bBase = sb + STG_A + (warpN * 48 + ((grp >> 1) << 3) + lr) * ARS + ((grp & 1) << 4);

    float acc[2][6][4];
    #pragma unroll
    for (int i = 0; i < 2; i++)
        #pragma unroll
        for (int j = 0; j < 6; j++)
            #pragma unroll
            for (int e = 0; e < 4; e++) acc[i][j][e] = 0.f;

    // per-thread constant staging coordinates: A covers 2 rows per thread
    const int stSlot = tid & 3;
    int stRowA[2], stM[2];
    bool xValid[2];
    long long xOff[2];
    #pragma unroll
    for (int i = 0; i < 2; ++i) {
        stRowA[i] = (tid >> 2) + i * 32;       // 0..63
        stM[i] = mBase + stRowA[i];
        int r = stM[i] >> 5, b = stM[i] & 31;
        int c = t - r;
        xValid[i] = (c >= 0 && c < OLEN);
        xOff[i] = ((long long)(b * SN + r) * OLEN + (xValid[i] ? c : 0)) * DD + stSlot * 8;
    }

    // ---- cp.async staging of one chunk (extended-K cc) into stage s ----
    auto stage_chunk = [&](int cc, int s) {
        int p = cc / 9, kc = cc - p * 9;
        uint32_t base = sb + s * STG_BYTES;
        // A: 64 rows x 32 bf16 = 256 16B-slots, 2 per thread
        #pragma unroll
        for (int i = 0; i < 2; ++i) {
            uint32_t dst = base + stRowA[i] * ARS + stSlot * 16;
            if (kc < 8) {
                bool isRow = kc < 4;
                int kk = (isRow ? kc : kc - 4) * 32 + stSlot * 8;
                const __nv_bfloat16* src = isRow ? ((p == 1) ? g_hr_l[pin] : g_hr_h[pin])
                                                 : ((p == 1) ? g_hc_l[pin] : g_hc_h[pin]);
                cp_async16(dst, src + stM[i] * HH + kk, true);
            } else {
                const __nv_bfloat16* src = (p == 1) ? g_x_l : g_x_h;
                cp_async16(dst, src + xOff[i], xValid[i]);
            }
        }
        // B: 96 rows x 32 bf16 = 384 16B-slots, 3 per thread
        const __nv_bfloat16* w = (p == 2) ? g_Wl : g_Wh;
        #pragma unroll
        for (int i = 0; i < 3; ++i) {
            int lin = tid + i * 128;
            int row = lin >> 2, slot = lin & 3;
            uint32_t dst = base + STG_A + row * ARS + slot * 16;
            cp_async16(dst, w + (nBase + row) * KK + kc * 32 + slot * 8, true);
        }
        CP_COMMIT();
    };

    // ---- prologue: stage chunks 0,1,2 ----
    stage_chunk(0, 0);
    stage_chunk(1, 1);
    stage_chunk(2, 2);

    for (int cc = 0; cc < 27; ++cc) {
        CP_WAIT2();            // guarantees chunk cc landed (see tail empty-commits)
        __syncthreads();       // all warps see it; stage (cc+3)%4 fully consumed

        if (cc + 3 < 27) stage_chunk(cc + 3, (cc + 3) % NSTG);
        else             CP_COMMIT();   // empty group keeps wait_group arithmetic exact

        // compute chunk cc from stage cc%4
        const uint32_t soff = (uint32_t)(cc % NSTG) * STG_BYTES;
        const uint32_t aB = aBase + soff;
        const uint32_t bB = bBase + soff;
        #pragma unroll
        for (int ks = 0; ks < 2; ++ks) {
            uint32_t a[2][4];
            #pragma unroll
            for (int mt = 0; mt < 2; ++mt)
                ldsm_x4(a[mt][0], a[mt][1], a[mt][2], a[mt][3],
                        aB + mt * (16 * ARS) + ks * 32);
            uint32_t bt[6][2];
            #pragma unroll
            for (int pr = 0; pr < 3; ++pr) {
                uint32_t r0, r1, r2, r3;
                ldsm_x4(r0, r1, r2, r3, bB + pr * (16 * ARS) + ks * 32);
                bt[2 * pr][0] = r0; bt[2 * pr][1] = r1;
                bt[2 * pr + 1][0] = r2; bt[2 * pr + 1][1] = r3;
            }
            #pragma unroll
            for (int mt = 0; mt < 2; ++mt)
                #pragma unroll
                for (int nt = 0; nt < 6; ++nt)
                    mma16816(acc[mt][nt], a[mt][0], a[mt][1], a[mt][2], a[mt][3],
                             bt[nt][0], bt[nt][1]);
        }
    }

    // ---- epilogue: bias + gating + state update + outputs ----
    const float* __restrict__ hrow_in = g_hrow[pin];
    const float* __restrict__ hcol_in = g_hcol[pin];
    float* __restrict__ hrow_out = g_hrow[pin ^ 1];
    float* __restrict__ hcol_out = g_hcol[pin ^ 1];
    __nv_bfloat16* __restrict__ hr_h_out = g_hr_h[pin ^ 1];
    __nv_bfloat16* __restrict__ hr_l_out = g_hr_l[pin ^ 1];
    __nv_bfloat16* __restrict__ hc_h_out = g_hc_h[pin ^ 1];
    __nv_bfloat16* __restrict__ hc_l_out = g_hc_l[pin ^ 1];

    float bl[2][3][2];
    #pragma unroll
    for (int q = 0; q < 2; ++q)
        #pragma unroll
        for (int p = 0; p < 3; ++p)
            #pragma unroll
            for (int e = 0; e < 2; ++e)
                bl[q][p][e] = g_bias[nBase + warpN * 48 + (q * 3 + p) * 8 + c4 * 2 + e];

    const long long HR_BASE = (long long)MM * SLT * 256;
    const long long HC_BASE = HR_BASE + (long long)NB * SN * HH;

    #pragma unroll
    for (int mt = 0; mt < 2; ++mt) {
        #pragma unroll
        for (int h = 0; h < 2; ++h) {
            const int m = mBase + warpM * 32 + mt * 16 + h * 8 + g4;
            const int r = m >> 5, b = m & 31;
            int ms = m + NB; if (ms >= MM) ms -= MM;
            const long long ob = ((long long)m * SLT + t) * 256;
            #pragma unroll
            for (int q = 0; q < 2; ++q) {
                const int U = blockIdx.x * 16 + warpN * 8 + q * 4 + c4;

                float a_ur = acc[mt][q * 3 + 0][h * 2 + 0] + bl[q][0][0];
                float a_or = acc[mt][q * 3 + 0][h * 2 + 1] + bl[q][0][1];
                float a_uc = acc[mt][q * 3 + 1][h * 2 + 0] + bl[q][1][0];
                float a_oc = acc[mt][q * 3 + 1][h * 2 + 1] + bl[q][1][1];
                float a_ir = acc[mt][q * 3 + 2][h * 2 + 0] + bl[q][2][0];
                float a_ic = acc[mt][q * 3 + 2][h * 2 + 1] + bl[q][2][1];

                float hr = hrow_in[m * HH + U];
                float hc = hcol_in[m * HH + U];

                float ur = sigmoid_f(a_ur);
                float og = sigmoid_f(a_or);
                float uc = sigmoid_f(a_uc);
                float oc = sigmoid_f(a_oc);
                float ir = tanh_ap(a_ir);
                float ic = tanh_ap(a_ic);

                float hrn = tanh_ap((1.f - ur) * hr + ur * ir) * og;
                float hcn = tanh_ap((1.f - uc) * hc + uc * ic) * oc;

                out[ob + U]       = hrn;
                out[ob + 128 + U] = hcn;

                hrow_out[m * HH + U] = hrn;
                hcol_out[ms * HH + U] = hcn;

                __nv_bfloat16 rh = __float2bfloat16(hrn);
                hr_h_out[m * HH + U] = rh;
                hr_l_out[m * HH + U] = __float2bfloat16(hrn - __bfloat162float(rh));
                __nv_bfloat16 ch = __float2bfloat16(hcn);
                hc_h_out[ms * HH + U] = ch;
                hc_l_out[ms * HH + U] = __float2bfloat16(hcn - __bfloat162float(ch));

                if (write_hidden) {
                    if (t - r == OLEN - 1)
                        out[HR_BASE + ((long long)b * SN + r) * HH + U] = hrn;
                    if (r == SN - 1 && t >= SN - 1)
                        out[HC_BASE + ((long long)b * OLEN + (t - (SN - 1))) * HH + U] = hcn;
                }
            }
        }
    }
}

// ---------------- launch ----------------
extern "C" void kernel_launch(void* const* d_in, const int* in_sizes, int n_in,
                              void* d_out, int out_size) {
    const float* input = (const float*)d_in[0];
    const float* Wf    = (const float*)d_in[1];
    const float* bf    = (const float*)d_in[2];
    const float* Wrm   = (const float*)d_in[3];
    const float* brm   = (const float*)d_in[4];
    const float* Wcm   = (const float*)d_in[5];
    const float* bcm   = (const float*)d_in[6];
    const float* Wrxm  = (const float*)d_in[7];
    const float* brxm  = (const float*)d_in[8];
    const float* Wcxm  = (const float*)d_in[9];
    const float* bcxm  = (const float*)d_in[10];
    float* out = (float*)d_out;

    long long need = (long long)MM * SLT * 256 + (long long)NB * SN * HH + (long long)NB * OLEN * HH;
    int write_hidden = ((long long)out_size >= need) ? 1 : 0;

    static int attr_set = 0;
    if (!attr_set) {
        cudaFuncSetAttribute(step_kernel, cudaFuncAttributeMaxDynamicSharedMemorySize,
                             SMEM_BYTES);
        attr_set = 1;
    }

    zero_all_kernel<<<256, 256>>>();
    prep_x_kernel<<<256, 256>>>(input);
    prep_weights_kernel<<<NG, KK>>>(Wf, bf, Wrm, brm, Wcm, bcm, Wrxm, brxm, Wcxm, bcxm);

    dim3 grid(8, 48);
    for (int t = 0; t < SLT; ++t) {
        step_kernel<<<grid, 128, SMEM_BYTES>>>(out, t, t & 1, write_hidden);
    }
}

// round 16
// speedup vs baseline: 1.1830x; 1.0752x over previous
#include <cuda_runtime.h>
#include <cuda_bf16.h>
#include <cstdint>

// Problem constants
#define SN 96
#define NB 32
#define MM 3072
#define OLEN 48
#define SLT 143
#define HH 128
#define DD 32
#define KK 288       // fused K = 2H + D
#define NG 768       // 6H gate cols
#define NX (NB * SN * OLEN * DD)

#define MT 64        // block M tile
#define NT 96        // block N tile
#define ARS 80       // smem row stride bytes (32 bf16 + 16B pad)
#define STG_A (MT * ARS)            // 5120
#define STG_B (NT * ARS)            // 7680
#define STG_BYTES (STG_A + STG_B)   // 12800
#define NSTG 4
#define SMEM_BYTES (NSTG * STG_BYTES)   // 51200

// ---------------- device scratch ----------------
__device__ __nv_bfloat16 g_Wh[NG * KK];
__device__ __nv_bfloat16 g_Wl[NG * KK];
__device__ float g_bias[NG];
__device__ float g_hrow[2][MM * HH];
__device__ float g_hcol[2][MM * HH];
__device__ __nv_bfloat16 g_hr_h[2][MM * HH], g_hr_l[2][MM * HH];
__device__ __nv_bfloat16 g_hc_h[2][MM * HH], g_hc_l[2][MM * HH];
__device__ __nv_bfloat16 g_x_h[NX], g_x_l[NX];

// ---------------- helpers ----------------
__device__ __forceinline__ uint32_t smem_u32(const void* p) {
    uint32_t a;
    asm("{ .reg .u64 t; cvta.to.shared.u64 t, %1; cvt.u32.u64 %0, t; }" : "=r"(a) : "l"(p));
    return a;
}
__device__ __forceinline__ void cp_async16(uint32_t dst, const void* src, bool valid) {
    int sz = valid ? 16 : 0;
    asm volatile("cp.async.cg.shared.global [%0], [%1], 16, %2;"
                 :: "r"(dst), "l"(src), "r"(sz) : "memory");
}
#define CP_COMMIT()  asm volatile("cp.async.commit_group;" ::: "memory")
#define CP_WAIT2()   asm volatile("cp.async.wait_group 2;" ::: "memory")
__device__ __forceinline__ void ldsm_x4(uint32_t& r0, uint32_t& r1, uint32_t& r2, uint32_t& r3,
                                        uint32_t addr) {
    asm volatile("ldmatrix.sync.aligned.m8n8.x4.shared.b16 {%0,%1,%2,%3}, [%4];"
                 : "=r"(r0), "=r"(r1), "=r"(r2), "=r"(r3) : "r"(addr));
}
__device__ __forceinline__ void mma16816(float* c, uint32_t a0, uint32_t a1, uint32_t a2,
                                         uint32_t a3, uint32_t b0, uint32_t b1) {
    asm volatile(
        "mma.sync.aligned.m16n8k16.row.col.f32.bf16.bf16.f32 "
        "{%0,%1,%2,%3}, {%4,%5,%6,%7}, {%8,%9}, {%0,%1,%2,%3};"
        : "+f"(c[0]), "+f"(c[1]), "+f"(c[2]), "+f"(c[3])
        : "r"(a0), "r"(a1), "r"(a2), "r"(a3), "r"(b0), "r"(b1));
}
__device__ __forceinline__ float tanh_ap(float x) {
    float y;
    asm("tanh.approx.f32 %0, %1;" : "=f"(y) : "f"(x));
    return y;
}
__device__ __forceinline__ float sigmoid_f(float x) {
    return fmaf(0.5f, tanh_ap(0.5f * x), 0.5f);
}

// ---------------- init ----------------
__global__ void zero_all_kernel() {
    const __nv_bfloat16 bz = __float2bfloat16(0.f);
    int n = MM * HH;
    for (int i = blockIdx.x * blockDim.x + threadIdx.x; i < n; i += gridDim.x * blockDim.x) {
        g_hrow[0][i] = 0.f; g_hrow[1][i] = 0.f;
        g_hcol[0][i] = 0.f; g_hcol[1][i] = 0.f;
        g_hr_h[0][i] = bz; g_hr_h[1][i] = bz;
        g_hr_l[0][i] = bz; g_hr_l[1][i] = bz;
        g_hc_h[0][i] = bz; g_hc_h[1][i] = bz;
        g_hc_l[0][i] = bz; g_hc_l[1][i] = bz;
    }
}

__global__ void prep_x_kernel(const float* __restrict__ input) {
    for (int i = blockIdx.x * blockDim.x + threadIdx.x; i < NX; i += gridDim.x * blockDim.x) {
        float v = input[i];
        __nv_bfloat16 hi = __float2bfloat16(v);
        g_x_h[i] = hi;
        g_x_l[i] = __float2bfloat16(v - __bfloat162float(hi));
    }
}

// ---------------- prep: fused weights, mma-epilogue column permutation ----------------
// NT=96: cp -> nb=cp/96, local=cp%96, wN=local/48, r2=local%48,
//        tile=r2/8 (p=tile%3, q=tile/3), c=(r2%8)/2, e=r2&1
//        u = nb*16 + wN*8 + q*4 + c,  original gate g=p*2+e, oc = g*128 + u
// K layout: [0:128)=h_row, [128:256)=h_col, [256:288)=x
__global__ void prep_weights_kernel(
    const float* __restrict__ Wf,  const float* __restrict__ bf,
    const float* __restrict__ Wrm, const float* __restrict__ brm,
    const float* __restrict__ Wcm, const float* __restrict__ bcm,
    const float* __restrict__ Wrxm, const float* __restrict__ brxm,
    const float* __restrict__ Wcxm, const float* __restrict__ bcxm)
{
    int cp = blockIdx.x;              // 0..767
    int nb = cp / 96, local = cp % 96;
    int wN = local / 48, r2 = local % 48;
    int tile = r2 >> 3, ce = r2 & 7;
    int c = ce >> 1, e = ce & 1;
    int p = tile % 3, q = tile / 3;
    int u = nb * 16 + wN * 8 + q * 4 + c;
    int oc = (p * 2 + e) * 128 + u;

    __shared__ float sWf[KK];
    for (int i = threadIdx.x; i < KK; i += blockDim.x) sWf[i] = Wf[oc * KK + i];
    __syncthreads();

    int k = threadIdx.x;             // 288 threads
    float acc = 0.f;
    if (k < HH) {
        #pragma unroll 4
        for (int h = 0; h < HH; h++) acc += Wrm[h * HH + k] * sWf[h];
    } else if (k < 2 * HH) {
        int kk = k - HH;
        #pragma unroll 4
        for (int h = 0; h < HH; h++) acc += Wcm[h * HH + kk] * sWf[HH + h];
    } else {
        int d = k - 2 * HH;
        #pragma unroll 4
        for (int h = 0; h < HH; h++)
            acc += Wrxm[h * DD + d] * sWf[h] + Wcxm[h * DD + d] * sWf[HH + h];
        acc += sWf[2 * HH + d];
    }
    __nv_bfloat16 hi = __float2bfloat16(acc);
    g_Wh[cp * KK + k] = hi;
    g_Wl[cp * KK + k] = __float2bfloat16(acc - __bfloat162float(hi));

    if (threadIdx.x == 0) {
        float bacc = bf[oc];
        for (int h = 0; h < HH; h++)
            bacc += (brxm[h] + brm[h]) * sWf[h] + (bcxm[h] + bcm[h]) * sWf[HH + h];
        g_bias[cp] = bacc;
    }
}

// ---------------- per-step: HMMA GEMM + gating, cp.async 4-stage pipeline ----------------
// grid (8 n-tiles of 96, 48 m-tiles of 64) = 384 blocks, 128 threads = 4 warps (2M x 2N),
// warp tile 32x48 (2 m16 x 6 n8). K' = 864 (3 passes x 288), 27 chunks of k32.
// Pre-start blocks (2*blockIdx.y > t) take a GEMV fast path on the universal trajectory.
__global__ __launch_bounds__(128, 4) void step_kernel(
    float* __restrict__ out, int t, int pin, int write_hidden)
{
    extern __shared__ __align__(16) char sm[];
    const uint32_t sb = smem_u32(sm);

    const int tid   = threadIdx.x;
    const int lane  = tid & 31;
    const int wid   = tid >> 5;
    const int warpM = wid & 1;         // 0..1
    const int warpN = wid >> 1;        // 0..1
    const int mBase = blockIdx.y * MT;
    const int nBase = blockIdx.x * NT;

    const int g4 = lane >> 2, c4 = lane & 3;
    const int grp = lane >> 3, lr = lane & 7;

    const float* __restrict__ hrow_in = g_hrow[pin];
    const float* __restrict__ hcol_in = g_hcol[pin];
    float* __restrict__ hrow_out = g_hrow[pin ^ 1];
    float* __restrict__ hcol_out = g_hcol[pin ^ 1];
    __nv_bfloat16* __restrict__ hr_h_out = g_hr_h[pin ^ 1];
    __nv_bfloat16* __restrict__ hr_l_out = g_hr_l[pin ^ 1];
    __nv_bfloat16* __restrict__ hc_h_out = g_hc_h[pin ^ 1];
    __nv_bfloat16* __restrict__ hc_l_out = g_hc_l[pin ^ 1];

    float bl[2][3][2];
    #pragma unroll
    for (int q = 0; q < 2; ++q)
        #pragma unroll
        for (int p = 0; p < 3; ++p)
            #pragma unroll
            for (int e = 0; e < 2; ++e)
                bl[q][p][e] = g_bias[nBase + warpN * 48 + (q * 3 + p) * 8 + c4 * 2 + e];

    const long long HR_BASE = (long long)MM * SLT * 256;
    const long long HC_BASE = HR_BASE + (long long)NB * SN * HH;

    // ==================== DUP FAST PATH ====================
    // All 64 rows of this block are strictly pre-start: identical b-independent
    // state, x = 0, hidden picks never fire. Compute gates once via fp32 GEMV.
    if (2 * (int)blockIdx.y > t) {
        float* ff = reinterpret_cast<float*>(sm);          // [256] universal feat
        float* sg = reinterpret_cast<float*>(sm) + 256;    // [96] gate pre-acts

        ff[tid]       = hrow_in[mBase * HH + tid];
        ff[128 + tid] = hcol_in[mBase * HH + tid];
        __syncthreads();

        // each lane's k-slice of the feature vector (k = lane*8 .. +7)
        float fr[8];
        #pragma unroll
        for (int i = 0; i < 8; ++i) fr[i] = ff[lane * 8 + i];

        // warp wid computes permuted columns [wid*24, wid*24+24)
        #pragma unroll 6
        for (int j = 0; j < 24; ++j) {
            int cp = nBase + wid * 24 + j;
            const __nv_bfloat16* ph = g_Wh + (long long)cp * KK + lane * 8;
            const __nv_bfloat16* pl = g_Wl + (long long)cp * KK + lane * 8;
            uint4 hv = *reinterpret_cast<const uint4*>(ph);
            uint4 lv = *reinterpret_cast<const uint4*>(pl);
            const __nv_bfloat16* hb = reinterpret_cast<const __nv_bfloat16*>(&hv);
            const __nv_bfloat16* lb = reinterpret_cast<const __nv_bfloat16*>(&lv);
            float acc = 0.f;
            #pragma unroll
            for (int i = 0; i < 8; ++i)
                acc = fmaf(__bfloat162float(hb[i]) + __bfloat162float(lb[i]), fr[i], acc);
            #pragma unroll
            for (int off = 16; off > 0; off >>= 1)
                acc += __shfl_xor_sync(0xFFFFFFFFu, acc, off);
            if (lane == 0) sg[wid * 24 + j] = acc;
        }
        __syncthreads();

        // universal gate -> state per (q); broadcast-write all rows
        float hrn_q[2], hcn_q[2];
        #pragma unroll
        for (int q = 0; q < 2; ++q) {
            int cb = warpN * 48 + q * 24;
            float a_ur = sg[cb + 0 * 8 + c4 * 2 + 0] + bl[q][0][0];
            float a_or = sg[cb + 0 * 8 + c4 * 2 + 1] + bl[q][0][1];
            float a_uc = sg[cb + 1 * 8 + c4 * 2 + 0] + bl[q][1][0];
            float a_oc = sg[cb + 1 * 8 + c4 * 2 + 1] + bl[q][1][1];
            float a_ir = sg[cb + 2 * 8 + c4 * 2 + 0] + bl[q][2][0];
            float a_ic = sg[cb + 2 * 8 + c4 * 2 + 1] + bl[q][2][1];
            int U = blockIdx.x * 16 + warpN * 8 + q * 4 + c4;

            float hr = hrow_in[mBase * HH + U];
            float hc = hcol_in[mBase * HH + U];
            float ur = sigmoid_f(a_ur);
            float og = sigmoid_f(a_or);
            float uc = sigmoid_f(a_uc);
            float oc = sigmoid_f(a_oc);
            float ir = tanh_ap(a_ir);
            float ic = tanh_ap(a_ic);
            hrn_q[q] = tanh_ap((1.f - ur) * hr + ur * ir) * og;
            hcn_q[q] = tanh_ap((1.f - uc) * hc + uc * ic) * oc;
        }

        #pragma unroll
        for (int mt = 0; mt < 2; ++mt) {
            #pragma unroll
            for (int h = 0; h < 2; ++h) {
                const int m = mBase + warpM * 32 + mt * 16 + h * 8 + g4;
                int ms = m + NB; if (ms >= MM) ms -= MM;
                const long long ob = ((long long)m * SLT + t) * 256;
                #pragma unroll
                for (int q = 0; q < 2; ++q) {
                    const int U = blockIdx.x * 16 + warpN * 8 + q * 4 + c4;
                    float hrn = hrn_q[q], hcn = hcn_q[q];
                    out[ob + U]       = hrn;
                    out[ob + 128 + U] = hcn;
                    hrow_out[m * HH + U] = hrn;
                    hcol_out[ms * HH + U] = hcn;
                    __nv_bfloat16 rh = __float2bfloat16(hrn);
                    hr_h_out[m * HH + U] = rh;
                    hr_l_out[m * HH + U] = __float2bfloat16(hrn - __bfloat162float(rh));
                    __nv_bfloat16 ch = __float2bfloat16(hcn);
                    hc_h_out[ms * HH + U] = ch;
                    hc_l_out[ms * HH + U] = __float2bfloat16(hcn - __bfloat162float(ch));
                }
            }
        }
        return;
    }
    // ==================== NORMAL HMMA PATH ====================

    // ldmatrix lane base addresses (stage 0; add stage offset per chunk)
    const uint32_t aBase = sb + (warpM * 32 + ((grp & 1) << 3) + lr) * ARS + ((grp >> 1) << 4);
    const uint32_t bBase = sb + STG_A + (warpN * 48 + ((grp >> 1) << 3) + lr) * ARS + ((grp & 1) << 4);

    float acc[2][6][4];
    #pragma unroll
    for (int i = 0; i < 2; i++)
        #pragma unroll
        for (int j = 0; j < 6; j++)
            #pragma unroll
            for (int e = 0; e < 4; e++) acc[i][j][e] = 0.f;

    // per-thread constant staging coordinates: A covers 2 rows per thread
    const int stSlot = tid & 3;
    int stRowA[2], stM[2];
    bool xValid[2];
    long long xOff[2];
    #pragma unroll
    for (int i = 0; i < 2; ++i) {
        stRowA[i] = (tid >> 2) + i * 32;       // 0..63
        stM[i] = mBase + stRowA[i];
        int r = stM[i] >> 5, b = stM[i] & 31;
        int c = t - r;
        xValid[i] = (c >= 0 && c < OLEN);
        xOff[i] = ((long long)(b * SN + r) * OLEN + (xValid[i] ? c : 0)) * DD + stSlot * 8;
    }

    // ---- cp.async staging of one chunk (extended-K cc) into stage s ----
    auto stage_chunk = [&](int cc, int s) {
        int p = cc / 9, kc = cc - p * 9;
        uint32_t base = sb + s * STG_BYTES;
        // A: 64 rows x 32 bf16 = 256 16B-slots, 2 per thread
        #pragma unroll
        for (int i = 0; i < 2; ++i) {
            uint32_t dst = base + stRowA[i] * ARS + stSlot * 16;
            if (kc < 8) {
                bool isRow = kc < 4;
                int kk = (isRow ? kc : kc - 4) * 32 + stSlot * 8;
                const __nv_bfloat16* src = isRow ? ((p == 1) ? g_hr_l[pin] : g_hr_h[pin])
                                                 : ((p == 1) ? g_hc_l[pin] : g_hc_h[pin]);
                cp_async16(dst, src + stM[i] * HH + kk, true);
            } else {
                const __nv_bfloat16* src = (p == 1) ? g_x_l : g_x_h;
                cp_async16(dst, src + xOff[i], xValid[i]);
            }
        }
        // B: 96 rows x 32 bf16 = 384 16B-slots, 3 per thread
        const __nv_bfloat16* w = (p == 2) ? g_Wl : g_Wh;
        #pragma unroll
        for (int i = 0; i < 3; ++i) {
            int lin = tid + i * 128;
            int row = lin >> 2, slot = lin & 3;
            uint32_t dst = base + STG_A + row * ARS + slot * 16;
            cp_async16(dst, w + (nBase + row) * KK + kc * 32 + slot * 8, true);
        }
        CP_COMMIT();
    };

    // ---- prologue: stage chunks 0,1,2 ----
    stage_chunk(0, 0);
    stage_chunk(1, 1);
    stage_chunk(2, 2);

    for (int cc = 0; cc < 27; ++cc) {
        CP_WAIT2();            // guarantees chunk cc landed (see tail empty-commits)
        __syncthreads();       // all warps see it; stage (cc+3)%4 fully consumed

        if (cc + 3 < 27) stage_chunk(cc + 3, (cc + 3) % NSTG);
        else             CP_COMMIT();   // empty group keeps wait_group arithmetic exact

        // compute chunk cc from stage cc%4
        const uint32_t soff = (uint32_t)(cc % NSTG) * STG_BYTES;
        const uint32_t aB = aBase + soff;
        const uint32_t bB = bBase + soff;
        #pragma unroll
        for (int ks = 0; ks < 2; ++ks) {
            uint32_t a[2][4];
            #pragma unroll
            for (int mt = 0; mt < 2; ++mt)
                ldsm_x4(a[mt][0], a[mt][1], a[mt][2], a[mt][3],
                        aB + mt * (16 * ARS) + ks * 32);
            uint32_t bt[6][2];
            #pragma unroll
            for (int pr = 0; pr < 3; ++pr) {
                uint32_t r0, r1, r2, r3;
                ldsm_x4(r0, r1, r2, r3, bB + pr * (16 * ARS) + ks * 32);
                bt[2 * pr][0] = r0; bt[2 * pr][1] = r1;
                bt[2 * pr + 1][0] = r2; bt[2 * pr + 1][1] = r3;
            }
            #pragma unroll
            for (int mt = 0; mt < 2; ++mt)
                #pragma unroll
                for (int nt = 0; nt < 6; ++nt)
                    mma16816(acc[mt][nt], a[mt][0], a[mt][1], a[mt][2], a[mt][3],
                             bt[nt][0], bt[nt][1]);
        }
    }

    // ---- epilogue: bias + gating + state update + outputs ----
    #pragma unroll
    for (int mt = 0; mt < 2; ++mt) {
        #pragma unroll
        for (int h = 0; h < 2; ++h) {
            const int m = mBase + warpM * 32 + mt * 16 + h * 8 + g4;
            const int r = m >> 5, b = m & 31;
            int ms = m + NB; if (ms >= MM) ms -= MM;
            const long long ob = ((long long)m * SLT + t) * 256;
            #pragma unroll
            for (int q = 0; q < 2; ++q) {
                const int U = blockIdx.x * 16 + warpN * 8 + q * 4 + c4;

                float a_ur = acc[mt][q * 3 + 0][h * 2 + 0] + bl[q][0][0];
                float a_or = acc[mt][q * 3 + 0][h * 2 + 1] + bl[q][0][1];
                float a_uc = acc[mt][q * 3 + 1][h * 2 + 0] + bl[q][1][0];
                float a_oc = acc[mt][q * 3 + 1][h * 2 + 1] + bl[q][1][1];
                float a_ir = acc[mt][q * 3 + 2][h * 2 + 0] + bl[q][2][0];
                float a_ic = acc[mt][q * 3 + 2][h * 2 + 1] + bl[q][2][1];

                float hr = hrow_in[m * HH + U];
                float hc = hcol_in[m * HH + U];

                float ur = sigmoid_f(a_ur);
                float og = sigmoid_f(a_or);
                float uc = sigmoid_f(a_uc);
                float oc = sigmoid_f(a_oc);
                float ir = tanh_ap(a_ir);
                float ic = tanh_ap(a_ic);

                float hrn = tanh_ap((1.f - ur) * hr + ur * ir) * og;
                float hcn = tanh_ap((1.f - uc) * hc + uc * ic) * oc;

                out[ob + U]       = hrn;
                out[ob + 128 + U] = hcn;

                hrow_out[m * HH + U] = hrn;
                hcol_out[ms * HH + U] = hcn;

                __nv_bfloat16 rh = __float2bfloat16(hrn);
                hr_h_out[m * HH + U] = rh;
                hr_l_out[m * HH + U] = __float2bfloat16(hrn - __bfloat162float(rh));
                __nv_bfloat16 ch = __float2bfloat16(hcn);
                hc_h_out[ms * HH + U] = ch;
                hc_l_out[ms * HH + U] = __float2bfloat16(hcn - __bfloat162float(ch));

                if (write_hidden) {
                    if (t - r == OLEN - 1)
                        out[HR_BASE + ((long long)b * SN + r) * HH + U] = hrn;
                    if (r == SN - 1 && t >= SN - 1)
                        out[HC_BASE + ((long long)b * OLEN + (t - (SN - 1))) * HH + U] = hcn;
                }
            }
        }
    }
}

// ---------------- launch ----------------
extern "C" void kernel_launch(void* const* d_in, const int* in_sizes, int n_in,
                              void* d_out, int out_size) {
    const float* input = (const float*)d_in[0];
    const float* Wf    = (const float*)d_in[1];
    const float* bf    = (const float*)d_in[2];
    const float* Wrm   = (const float*)d_in[3];
    const float* brm   = (const float*)d_in[4];
    const float* Wcm   = (const float*)d_in[5];
    const float* bcm   = (const float*)d_in[6];
    const float* Wrxm  = (const float*)d_in[7];
    const float* brxm  = (const float*)d_in[8];
    const float* Wcxm  = (const float*)d_in[9];
    const float* bcxm  = (const float*)d_in[10];
    float* out = (float*)d_out;

    long long need = (long long)MM * SLT * 256 + (long long)NB * SN * HH + (long long)NB * OLEN * HH;
    int write_hidden = ((long long)out_size >= need) ? 1 : 0;

    static int attr_set = 0;
    if (!attr_set) {
        cudaFuncSetAttribute(step_kernel, cudaFuncAttributeMaxDynamicSharedMemorySize,
                             SMEM_BYTES);
        attr_set = 1;
    }

    zero_all_kernel<<<256, 256>>>();
    prep_x_kernel<<<256, 256>>>(input);
    prep_weights_kernel<<<NG, KK>>>(Wf, bf, Wrm, brm, Wcm, bcm, Wrxm, brxm, Wcxm, bcxm);

    dim3 grid(8, 48);
    for (int t = 0; t < SLT; ++t) {
        step_kernel<<<grid, 128, SMEM_BYTES>>>(out, t, t & 1, write_hidden);
    }
}

// round 17
// speedup vs baseline: 1.2164x; 1.0282x over previous
#include <cuda_runtime.h>
#include <cuda_bf16.h>
#include <cstdint>

// Problem constants
#define SN 96
#define NB 32
#define MM 3072
#define OLEN 48
#define SLT 143
#define HH 128
#define DD 32
#define KK 288       // fused K = 2H + D
#define NG 768       // 6H gate cols
#define NX (NB * SN * OLEN * DD)

#define MT 64        // block M tile
#define NT 96        // block N tile
#define ARS 80       // smem row stride bytes (32 bf16 + 16B pad)
#define STG_A (MT * ARS)            // 5120
#define STG_B (NT * ARS)            // 7680
#define STG_BYTES (STG_A + STG_B)   // 12800  (one 32-wide sub-chunk)
#define STG2 (2 * STG_BYTES)        // 25600  (one 64-wide chunk buffer)
#define SMEM_BYTES (2 * STG2)       // 51200  (double buffer)

// ---------------- device scratch ----------------
__device__ __nv_bfloat16 g_Wh[NG * KK];
__device__ __nv_bfloat16 g_Wl[NG * KK];
__device__ float g_bias[NG];
__device__ float g_hrow[2][MM * HH];
__device__ float g_hcol[2][MM * HH];
__device__ __nv_bfloat16 g_hr_h[2][MM * HH], g_hr_l[2][MM * HH];
__device__ __nv_bfloat16 g_hc_h[2][MM * HH], g_hc_l[2][MM * HH];
__device__ __nv_bfloat16 g_x_h[NX], g_x_l[NX];

// ---------------- helpers ----------------
__device__ __forceinline__ uint32_t smem_u32(const void* p) {
    uint32_t a;
    asm("{ .reg .u64 t; cvta.to.shared.u64 t, %1; cvt.u32.u64 %0, t; }" : "=r"(a) : "l"(p));
    return a;
}
__device__ __forceinline__ void cp_async16(uint32_t dst, const void* src, bool valid) {
    int sz = valid ? 16 : 0;
    asm volatile("cp.async.cg.shared.global [%0], [%1], 16, %2;"
                 :: "r"(dst), "l"(src), "r"(sz) : "memory");
}
#define CP_COMMIT()  asm volatile("cp.async.commit_group;" ::: "memory")
#define CP_WAIT0()   asm volatile("cp.async.wait_group 0;" ::: "memory")
__device__ __forceinline__ void ldsm_x4(uint32_t& r0, uint32_t& r1, uint32_t& r2, uint32_t& r3,
                                        uint32_t addr) {
    asm volatile("ldmatrix.sync.aligned.m8n8.x4.shared.b16 {%0,%1,%2,%3}, [%4];"
                 : "=r"(r0), "=r"(r1), "=r"(r2), "=r"(r3) : "r"(addr));
}
__device__ __forceinline__ void mma16816(float* c, uint32_t a0, uint32_t a1, uint32_t a2,
                                         uint32_t a3, uint32_t b0, uint32_t b1) {
    asm volatile(
        "mma.sync.aligned.m16n8k16.row.col.f32.bf16.bf16.f32 "
        "{%0,%1,%2,%3}, {%4,%5,%6,%7}, {%8,%9}, {%0,%1,%2,%3};"
        : "+f"(c[0]), "+f"(c[1]), "+f"(c[2]), "+f"(c[3])
        : "r"(a0), "r"(a1), "r"(a2), "r"(a3), "r"(b0), "r"(b1));
}
__device__ __forceinline__ float tanh_ap(float x) {
    float y;
    asm("tanh.approx.f32 %0, %1;" : "=f"(y) : "f"(x));
    return y;
}
__device__ __forceinline__ float sigmoid_f(float x) {
    return fmaf(0.5f, tanh_ap(0.5f * x), 0.5f);
}

// ---------------- init ----------------
__global__ void zero_all_kernel() {
    const __nv_bfloat16 bz = __float2bfloat16(0.f);
    int n = MM * HH;
    for (int i = blockIdx.x * blockDim.x + threadIdx.x; i < n; i += gridDim.x * blockDim.x) {
        g_hrow[0][i] = 0.f; g_hrow[1][i] = 0.f;
        g_hcol[0][i] = 0.f; g_hcol[1][i] = 0.f;
        g_hr_h[0][i] = bz; g_hr_h[1][i] = bz;
        g_hr_l[0][i] = bz; g_hr_l[1][i] = bz;
        g_hc_h[0][i] = bz; g_hc_h[1][i] = bz;
        g_hc_l[0][i] = bz; g_hc_l[1][i] = bz;
    }
}

__global__ void prep_x_kernel(const float* __restrict__ input) {
    for (int i = blockIdx.x * blockDim.x + threadIdx.x; i < NX; i += gridDim.x * blockDim.x) {
        float v = input[i];
        __nv_bfloat16 hi = __float2bfloat16(v);
        g_x_h[i] = hi;
        g_x_l[i] = __float2bfloat16(v - __bfloat162float(hi));
    }
}

// ---------------- prep: fused weights, mma-epilogue column permutation ----------------
// NT=96: cp -> nb=cp/96, local=cp%96, wN=local/48, r2=local%48,
//        tile=r2/8 (p=tile%3, q=tile/3), c=(r2%8)/2, e=r2&1
//        u = nb*16 + wN*8 + q*4 + c,  original gate g=p*2+e, oc = g*128 + u
// K layout: [0:128)=h_row, [128:256)=h_col, [256:288)=x
__global__ void prep_weights_kernel(
    const float* __restrict__ Wf,  const float* __restrict__ bf,
    const float* __restrict__ Wrm, const float* __restrict__ brm,
    const float* __restrict__ Wcm, const float* __restrict__ bcm,
    const float* __restrict__ Wrxm, const float* __restrict__ brxm,
    const float* __restrict__ Wcxm, const float* __restrict__ bcxm)
{
    int cp = blockIdx.x;              // 0..767
    int nb = cp / 96, local = cp % 96;
    int wN = local / 48, r2 = local % 48;
    int tile = r2 >> 3, ce = r2 & 7;
    int c = ce >> 1, e = ce & 1;
    int p = tile % 3, q = tile / 3;
    int u = nb * 16 + wN * 8 + q * 4 + c;
    int oc = (p * 2 + e) * 128 + u;

    __shared__ float sWf[KK];
    for (int i = threadIdx.x; i < KK; i += blockDim.x) sWf[i] = Wf[oc * KK + i];
    __syncthreads();

    int k = threadIdx.x;             // 288 threads
    float acc = 0.f;
    if (k < HH) {
        #pragma unroll 4
        for (int h = 0; h < HH; h++) acc += Wrm[h * HH + k] * sWf[h];
    } else if (k < 2 * HH) {
        int kk = k - HH;
        #pragma unroll 4
        for (int h = 0; h < HH; h++) acc += Wcm[h * HH + kk] * sWf[HH + h];
    } else {
        int d = k - 2 * HH;
        #pragma unroll 4
        for (int h = 0; h < HH; h++)
            acc += Wrxm[h * DD + d] * sWf[h] + Wcxm[h * DD + d] * sWf[HH + h];
        acc += sWf[2 * HH + d];
    }
    __nv_bfloat16 hi = __float2bfloat16(acc);
    g_Wh[cp * KK + k] = hi;
    g_Wl[cp * KK + k] = __float2bfloat16(acc - __bfloat162float(hi));

    if (threadIdx.x == 0) {
        float bacc = bf[oc];
        for (int h = 0; h < HH; h++)
            bacc += (brxm[h] + brm[h]) * sWf[h] + (bcxm[h] + bcm[h]) * sWf[HH + h];
        g_bias[cp] = bacc;
    }
}

// ---------------- per-step: HMMA GEMM + gating, k64 double-buffer pipeline ----------------
// grid (8 n-tiles of 96, 48 m-tiles of 64) = 384 blocks, 128 threads = 4 warps (2M x 2N),
// warp tile 32x48 (2 m16 x 6 n8). K' = 864 = 27 sub-chunks of k32 = 14 chunks of k64.
// Pre-start blocks (2*blockIdx.y > t) take a GEMV fast path on the universal trajectory.
__global__ __launch_bounds__(128, 4) void step_kernel(
    float* __restrict__ out, int t, int pin, int write_hidden)
{
    extern __shared__ __align__(16) char sm[];
    const uint32_t sb = smem_u32(sm);

    const int tid   = threadIdx.x;
    const int lane  = tid & 31;
    const int wid   = tid >> 5;
    const int warpM = wid & 1;         // 0..1
    const int warpN = wid >> 1;        // 0..1
    const int mBase = blockIdx.y * MT;
    const int nBase = blockIdx.x * NT;

    const int g4 = lane >> 2, c4 = lane & 3;
    const int grp = lane >> 3, lr = lane & 7;

    const float* __restrict__ hrow_in = g_hrow[pin];
    const float* __restrict__ hcol_in = g_hcol[pin];
    float* __restrict__ hrow_out = g_hrow[pin ^ 1];
    float* __restrict__ hcol_out = g_hcol[pin ^ 1];
    __nv_bfloat16* __restrict__ hr_h_out = g_hr_h[pin ^ 1];
    __nv_bfloat16* __restrict__ hr_l_out = g_hr_l[pin ^ 1];
    __nv_bfloat16* __restrict__ hc_h_out = g_hc_h[pin ^ 1];
    __nv_bfloat16* __restrict__ hc_l_out = g_hc_l[pin ^ 1];

    float bl[2][3][2];
    #pragma unroll
    for (int q = 0; q < 2; ++q)
        #pragma unroll
        for (int p = 0; p < 3; ++p)
            #pragma unroll
            for (int e = 0; e < 2; ++e)
                bl[q][p][e] = g_bias[nBase + warpN * 48 + (q * 3 + p) * 8 + c4 * 2 + e];

    const long long HR_BASE = (long long)MM * SLT * 256;
    const long long HC_BASE = HR_BASE + (long long)NB * SN * HH;

    // ==================== DUP FAST PATH ====================
    if (2 * (int)blockIdx.y > t) {
        float* ff = reinterpret_cast<float*>(sm);          // [256] universal feat
        float* sg = reinterpret_cast<float*>(sm) + 256;    // [96] gate pre-acts

        ff[tid]       = hrow_in[mBase * HH + tid];
        ff[128 + tid] = hcol_in[mBase * HH + tid];
        __syncthreads();

        float fr[8];
        #pragma unroll
        for (int i = 0; i < 8; ++i) fr[i] = ff[lane * 8 + i];

        #pragma unroll 6
        for (int j = 0; j < 24; ++j) {
            int cp = nBase + wid * 24 + j;
            const __nv_bfloat16* ph = g_Wh + (long long)cp * KK + lane * 8;
            const __nv_bfloat16* pl = g_Wl + (long long)cp * KK + lane * 8;
            uint4 hv = *reinterpret_cast<const uint4*>(ph);
            uint4 lv = *reinterpret_cast<const uint4*>(pl);
            const __nv_bfloat16* hb = reinterpret_cast<const __nv_bfloat16*>(&hv);
            const __nv_bfloat16* lb = reinterpret_cast<const __nv_bfloat16*>(&lv);
            float acc = 0.f;
            #pragma unroll
            for (int i = 0; i < 8; ++i)
                acc = fmaf(__bfloat162float(hb[i]) + __bfloat162float(lb[i]), fr[i], acc);
            #pragma unroll
            for (int off = 16; off > 0; off >>= 1)
                acc += __shfl_xor_sync(0xFFFFFFFFu, acc, off);
            if (lane == 0) sg[wid * 24 + j] = acc;
        }
        __syncthreads();

        float hrn_q[2], hcn_q[2];
        #pragma unroll
        for (int q = 0; q < 2; ++q) {
            int cb = warpN * 48 + q * 24;
            float a_ur = sg[cb + 0 * 8 + c4 * 2 + 0] + bl[q][0][0];
            float a_or = sg[cb + 0 * 8 + c4 * 2 + 1] + bl[q][0][1];
            float a_uc = sg[cb + 1 * 8 + c4 * 2 + 0] + bl[q][1][0];
            float a_oc = sg[cb + 1 * 8 + c4 * 2 + 1] + bl[q][1][1];
            float a_ir = sg[cb + 2 * 8 + c4 * 2 + 0] + bl[q][2][0];
            float a_ic = sg[cb + 2 * 8 + c4 * 2 + 1] + bl[q][2][1];
            int U = blockIdx.x * 16 + warpN * 8 + q * 4 + c4;

            float hr = hrow_in[mBase * HH + U];
            float hc = hcol_in[mBase * HH + U];
            float ur = sigmoid_f(a_ur);
            float og = sigmoid_f(a_or);
            float uc = sigmoid_f(a_uc);
            float oc = sigmoid_f(a_oc);
            float ir = tanh_ap(a_ir);
            float ic = tanh_ap(a_ic);
            hrn_q[q] = tanh_ap((1.f - ur) * hr + ur * ir) * og;
            hcn_q[q] = tanh_ap((1.f - uc) * hc + uc * ic) * oc;
        }

        #pragma unroll
        for (int mt = 0; mt < 2; ++mt) {
            #pragma unroll
            for (int h = 0; h < 2; ++h) {
                const int m = mBase + warpM * 32 + mt * 16 + h * 8 + g4;
                int ms = m + NB; if (ms >= MM) ms -= MM;
                const long long ob = ((long long)m * SLT + t) * 256;
                #pragma unroll
                for (int q = 0; q < 2; ++q) {
                    const int U = blockIdx.x * 16 + warpN * 8 + q * 4 + c4;
                    float hrn = hrn_q[q], hcn = hcn_q[q];
                    out[ob + U]       = hrn;
                    out[ob + 128 + U] = hcn;
                    hrow_out[m * HH + U] = hrn;
                    hcol_out[ms * HH + U] = hcn;
                    __nv_bfloat16 rh = __float2bfloat16(hrn);
                    hr_h_out[m * HH + U] = rh;
                    hr_l_out[m * HH + U] = __float2bfloat16(hrn - __bfloat162float(rh));
                    __nv_bfloat16 ch = __float2bfloat16(hcn);
                    hc_h_out[ms * HH + U] = ch;
                    hc_l_out[ms * HH + U] = __float2bfloat16(hcn - __bfloat162float(ch));
                }
            }
        }
        return;
    }
    // ==================== NORMAL HMMA PATH ====================

    // ldmatrix lane base addresses (buffer-relative; add buf/sub offset per chunk)
    const uint32_t aBase = sb + (warpM * 32 + ((grp & 1) << 3) + lr) * ARS + ((grp >> 1) << 4);
    const uint32_t bBase = sb + STG_A + (warpN * 48 + ((grp >> 1) << 3) + lr) * ARS + ((grp & 1) << 4);

    float acc[2][6][4];
    #pragma unroll
    for (int i = 0; i < 2; i++)
        #pragma unroll
        for (int j = 0; j < 6; j++)
            #pragma unroll
            for (int e = 0; e < 4; e++) acc[i][j][e] = 0.f;

    // per-thread constant staging coordinates: A covers 2 rows per thread
    const int stSlot = tid & 3;
    int stRowA[2], stM[2];
    bool xValid[2];
    long long xOff[2];
    #pragma unroll
    for (int i = 0; i < 2; ++i) {
        stRowA[i] = (tid >> 2) + i * 32;       // 0..63
        stM[i] = mBase + stRowA[i];
        int r = stM[i] >> 5, b = stM[i] & 31;
        int c = t - r;
        xValid[i] = (c >= 0 && c < OLEN);
        xOff[i] = ((long long)(b * SN + r) * OLEN + (xValid[i] ? c : 0)) * DD + stSlot * 8;
    }

    // ---- cp.async staging of one k32 sub-chunk (extended-K scc) at smem 'base' ----
    auto stage_sub = [&](int scc, uint32_t base) {
        int p = scc / 9, kc = scc - p * 9;
        // A: 64 rows x 32 bf16 = 256 16B-slots, 2 per thread
        #pragma unroll
        for (int i = 0; i < 2; ++i) {
            uint32_t dst = base + stRowA[i] * ARS + stSlot * 16;
            if (kc < 8) {
                bool isRow = kc < 4;
                int kk = (isRow ? kc : kc - 4) * 32 + stSlot * 8;
                const __nv_bfloat16* src = isRow ? ((p == 1) ? g_hr_l[pin] : g_hr_h[pin])
                                                 : ((p == 1) ? g_hc_l[pin] : g_hc_h[pin]);
                cp_async16(dst, src + stM[i] * HH + kk, true);
            } else {
                const __nv_bfloat16* src = (p == 1) ? g_x_l : g_x_h;
                cp_async16(dst, src + xOff[i], xValid[i]);
            }
        }
        // B: 96 rows x 32 bf16 = 384 16B-slots, 3 per thread
        const __nv_bfloat16* w = (p == 2) ? g_Wl : g_Wh;
        #pragma unroll
        for (int i = 0; i < 3; ++i) {
            int lin = tid + i * 128;
            int row = lin >> 2, slot = lin & 3;
            uint32_t dst = base + STG_A + row * ARS + slot * 16;
            cp_async16(dst, w + (nBase + row) * KK + kc * 32 + slot * 8, true);
        }
    };

    // ---- stage one k64 chunk (pair of sub-chunks) into buffer cc&1 ----
    auto stage_pair = [&](int cc) {
        uint32_t base = sb + (uint32_t)(cc & 1) * STG2;
        stage_sub(2 * cc, base);
        if (2 * cc + 1 < 27) stage_sub(2 * cc + 1, base + STG_BYTES);
        CP_COMMIT();
    };

    // ---- prologue: stage chunk 0 ----
    stage_pair(0);

    for (int cc = 0; cc < 14; ++cc) {
        CP_WAIT0();            // all committed groups done -> chunk cc landed
        __syncthreads();       // publish; prev buffer fully consumed by all warps

        if (cc + 1 < 14) stage_pair(cc + 1);   // overlaps compute below

        const uint32_t bufOff = (uint32_t)(cc & 1) * STG2;
        #pragma unroll
        for (int sub = 0; sub < 2; ++sub) {
            if (2 * cc + sub >= 27) break;
            const uint32_t soff = bufOff + (uint32_t)sub * STG_BYTES;
            const uint32_t aB = aBase + soff;
            const uint32_t bB = bBase + soff;
            #pragma unroll
            for (int ks = 0; ks < 2; ++ks) {
                uint32_t a[2][4];
                #pragma unroll
                for (int mt = 0; mt < 2; ++mt)
                    ldsm_x4(a[mt][0], a[mt][1], a[mt][2], a[mt][3],
                            aB + mt * (16 * ARS) + ks * 32);
                uint32_t bt[6][2];
                #pragma unroll
                for (int pr = 0; pr < 3; ++pr) {
                    uint32_t r0, r1, r2, r3;
                    ldsm_x4(r0, r1, r2, r3, bB + pr * (16 * ARS) + ks * 32);
                    bt[2 * pr][0] = r0; bt[2 * pr][1] = r1;
                    bt[2 * pr + 1][0] = r2; bt[2 * pr + 1][1] = r3;
                }
                #pragma unroll
                for (int mt = 0; mt < 2; ++mt)
                    #pragma unroll
                    for (int nt = 0; nt < 6; ++nt)
                        mma16816(acc[mt][nt], a[mt][0], a[mt][1], a[mt][2], a[mt][3],
                                 bt[nt][0], bt[nt][1]);
            }
        }
    }

    // ---- epilogue: bias + gating + state update + outputs ----
    #pragma unroll
    for (int mt = 0; mt < 2; ++mt) {
        #pragma unroll
        for (int h = 0; h < 2; ++h) {
            const int m = mBase + warpM * 32 + mt * 16 + h * 8 + g4;
            const int r = m >> 5, b = m & 31;
            int ms = m + NB; if (ms >= MM) ms -= MM;
            const long long ob = ((long long)m * SLT + t) * 256;
            #pragma unroll
            for (int q = 0; q < 2; ++q) {
                const int U = blockIdx.x * 16 + warpN * 8 + q * 4 + c4;

                float a_ur = acc[mt][q * 3 + 0][h * 2 + 0] + bl[q][0][0];
                float a_or = acc[mt][q * 3 + 0][h * 2 + 1] + bl[q][0][1];
                float a_uc = acc[mt][q * 3 + 1][h * 2 + 0] + bl[q][1][0];
                float a_oc = acc[mt][q * 3 + 1][h * 2 + 1] + bl[q][1][1];
                float a_ir = acc[mt][q * 3 + 2][h * 2 + 0] + bl[q][2][0];
                float a_ic = acc[mt][q * 3 + 2][h * 2 + 1] + bl[q][2][1];

                float hr = hrow_in[m * HH + U];
                float hc = hcol_in[m * HH + U];

                float ur = sigmoid_f(a_ur);
                float og = sigmoid_f(a_or);
                float uc = sigmoid_f(a_uc);
                float oc = sigmoid_f(a_oc);
                float ir = tanh_ap(a_ir);
                float ic = tanh_ap(a_ic);

                float hrn = tanh_ap((1.f - ur) * hr + ur * ir) * og;
                float hcn = tanh_ap((1.f - uc) * hc + uc * ic) * oc;

                out[ob + U]       = hrn;
                out[ob + 128 + U] = hcn;

                hrow_out[m * HH + U] = hrn;
                hcol_out[ms * HH + U] = hcn;

                __nv_bfloat16 rh = __float2bfloat16(hrn);
                hr_h_out[m * HH + U] = rh;
                hr_l_out[m * HH + U] = __float2bfloat16(hrn - __bfloat162float(rh));
                __nv_bfloat16 ch = __float2bfloat16(hcn);
                hc_h_out[ms * HH + U] = ch;
                hc_l_out[ms * HH + U] = __float2bfloat16(hcn - __bfloat162float(ch));

                if (write_hidden) {
                    if (t - r == OLEN - 1)
                        out[HR_BASE + ((long long)b * SN + r) * HH + U] = hrn;
                    if (r == SN - 1 && t >= SN - 1)
                        out[HC_BASE + ((long long)b * OLEN + (t - (SN - 1))) * HH + U] = hcn;
                }
            }
        }
    }
}

// ---------------- launch ----------------
extern "C" void kernel_launch(void* const* d_in, const int* in_sizes, int n_in,
                              void* d_out, int out_size) {
    const float* input = (const float*)d_in[0];
    const float* Wf    = (const float*)d_in[1];
    const float* bf    = (const float*)d_in[2];
    const float* Wrm   = (const float*)d_in[3];
    const float* brm   = (const float*)d_in[4];
    const float* Wcm   = (const float*)d_in[5];
    const float* bcm   = (const float*)d_in[6];
    const float* Wrxm  = (const float*)d_in[7];
    const float* brxm  = (const float*)d_in[8];
    const float* Wcxm  = (const float*)d_in[9];
    const float* bcxm  = (const float*)d_in[10];
    float* out = (float*)d_out;

    long long need = (long long)MM * SLT * 256 + (long long)NB * SN * HH + (long long)NB * OLEN * HH;
    int write_hidden = ((long long)out_size >= need) ? 1 : 0;

    static int attr_set = 0;
    if (!attr_set) {
        cudaFuncSetAttribute(step_kernel, cudaFuncAttributeMaxDynamicSharedMemorySize,
                             SMEM_BYTES);
        attr_set = 1;
    }

    zero_all_kernel<<<256, 256>>>();
    prep_x_kernel<<<256, 256>>>(input);
    prep_weights_kernel<<<NG, KK>>>(Wf, bf, Wrm, brm, Wcm, bcm, Wrxm, brxm, Wcxm, bcxm);

    dim3 grid(8, 48);
    for (int t = 0; t < SLT; ++t) {
        step_kernel<<<grid, 128, SMEM_BYTES>>>(out, t, t & 1, write_hidden);
    }
}